// round 12
// baseline (speedup 1.0000x reference)
#include <cuda_runtime.h>
#include <cuda_fp16.h>
#include <math.h>
#include <stdint.h>

#define NB 4096
#define ND 1024
#define NH 2048
#define NC 1000
#define NF 32

// ---------------- scratch ---------------------------------------------------
__device__ float g_means[NB * NF];
__device__ __align__(16) __half g_a1[(size_t)NB * ND];        // fp16(combined)
__device__ __align__(16) __half g_w1[(size_t)NH * ND];        // fp16(W1)
__device__ __align__(16) __half g_hid[(size_t)NB * 2 * NH];   // [hi(2048) | lo(2048)]
__device__ __align__(16) __half g_w2[(size_t)NC * NH];        // fp16(W2)
__device__ float g_logits[(size_t)NB * NC];
__device__ float g_rowloss[NB];
__device__ float g_rowcorrect[NB];
__device__ float g_rowsq[NB];
__device__ int   g_starts[NB + 1];

// ---------------- helpers ---------------------------------------------------
__device__ __forceinline__ uint32_t smem_u32(const void* p) {
    uint32_t a;
    asm("{ .reg .u64 t; cvta.to.shared.u64 t, %1; cvt.u32.u64 %0, t; }"
        : "=r"(a) : "l"(p));
    return a;
}

__device__ __forceinline__ void ldsm4(uint32_t& r0, uint32_t& r1, uint32_t& r2,
                                      uint32_t& r3, uint32_t a) {
    asm volatile("ldmatrix.sync.aligned.m8n8.x4.shared.b16 {%0,%1,%2,%3}, [%4];"
                 : "=r"(r0), "=r"(r1), "=r"(r2), "=r"(r3) : "r"(a));
}

__device__ __forceinline__ void mma16816(float* c, uint32_t a0, uint32_t a1,
                                         uint32_t a2, uint32_t a3,
                                         uint32_t b0, uint32_t b1) {
    asm volatile(
        "mma.sync.aligned.m16n8k16.row.col.f32.f16.f16.f32 "
        "{%0,%1,%2,%3}, {%4,%5,%6,%7}, {%8,%9}, {%0,%1,%2,%3};"
        : "+f"(c[0]), "+f"(c[1]), "+f"(c[2]), "+f"(c[3])
        : "r"(a0), "r"(a1), "r"(a2), "r"(a3), "r"(b0), "r"(b1));
}

#define CPA16(sa, ga, pbytes) \
    asm volatile("cp.async.cg.shared.global [%0], [%1], 16, %2;" \
                 :: "r"(sa), "l"(ga), "r"(pbytes))
#define CPA_COMMIT() asm volatile("cp.async.commit_group;" ::: "memory")

// ---------------- 1. segment starts -----------------------------------------
__global__ void k_starts(const int* __restrict__ seg, int T) {
    int b = blockIdx.x * blockDim.x + threadIdx.x;
    if (b > NB) return;
    int lo = 0, hi = T;
    while (lo < hi) { int m = (lo + hi) >> 1; if (seg[m] < b) lo = m + 1; else hi = m; }
    g_starts[b] = lo;
}

// ---------------- 2. per-segment mean ---------------------------------------
__global__ void k_means(const float* __restrict__ vf) {
    int b = blockIdx.x;
    int start = g_starts[b], end = g_starts[b + 1];
    int tid = threadIdx.x;
    int j = tid & 7, r = tid >> 3;
    float4 acc = make_float4(0.f, 0.f, 0.f, 0.f);
    for (int row = start + r; row < end; row += 32) {
        float4 v = *(const float4*)(vf + (size_t)row * NF + j * 4);
        acc.x += v.x; acc.y += v.y; acc.z += v.z; acc.w += v.w;
    }
    __shared__ float4 s[256];
    s[tid] = acc; __syncthreads();
    for (int off = 128; off >= 8; off >>= 1) {
        if (tid < off) {
            float4 o = s[tid + off]; float4 m = s[tid];
            m.x += o.x; m.y += o.y; m.z += o.z; m.w += o.w; s[tid] = m;
        }
        __syncthreads();
    }
    if (tid < 8) {
        float inv = 1.0f / fmaxf((float)(end - start), 1.0f);
        float4 m = s[tid];
        m.x *= inv; m.y *= inv; m.z *= inv; m.w *= inv;
        *(float4*)(g_means + (size_t)b * NF + tid * 4) = m;
    }
}

// ------- 3. weight fp32 -> fp16 (single copy) -------------------------------
__global__ void k_cvt_w(const float* __restrict__ W, __half* __restrict__ out,
                        int total4) {
    int idx = blockIdx.x * blockDim.x + threadIdx.x;
    if (idx >= total4) return;
    float4 v = *(const float4*)(W + (size_t)idx * 4);
    union { __half h[4]; uint2 u; } H;
    H.h[0] = __float2half_rn(v.x); H.h[1] = __float2half_rn(v.y);
    H.h[2] = __float2half_rn(v.z); H.h[3] = __float2half_rn(v.w);
    *(uint2*)(out + (size_t)idx * 4) = H.u;
}

// ------- 4. combined = feature + means @ Wv^T + bv -> fp16 ------------------
__global__ void k_combined(const float* __restrict__ feat,
                           const float* __restrict__ Wv,
                           const float* __restrict__ bv) {
    __shared__ float wv_s[NF][64];
    __shared__ float me_s[NF][128];
    int d0 = blockIdx.x * 64, b0 = blockIdx.y * 128;
    int tid = threadIdx.x;
    for (int idx = tid; idx < 64 * 8; idx += 256) {
        int dd = idx >> 3, fg = (idx & 7) * 4;
        float4 v = *(const float4*)(Wv + (size_t)(d0 + dd) * NF + fg);
        wv_s[fg + 0][dd] = v.x; wv_s[fg + 1][dd] = v.y;
        wv_s[fg + 2][dd] = v.z; wv_s[fg + 3][dd] = v.w;
    }
    for (int idx = tid; idx < 128 * 8; idx += 256) {
        int bb = idx >> 3, fg = (idx & 7) * 4;
        float4 v = *(const float4*)(g_means + (size_t)(b0 + bb) * NF + fg);
        me_s[fg + 0][bb] = v.x; me_s[fg + 1][bb] = v.y;
        me_s[fg + 2][bb] = v.z; me_s[fg + 3][bb] = v.w;
    }
    __syncthreads();
    int tx = tid & 15, ty = tid >> 4;
    float acc[8][4];
    #pragma unroll
    for (int r = 0; r < 8; r++)
        #pragma unroll
        for (int c = 0; c < 4; c++) acc[r][c] = 0.f;
    #pragma unroll 4
    for (int f = 0; f < NF; f++) {
        float w[4], m[8];
        #pragma unroll
        for (int c = 0; c < 4; c++) w[c] = wv_s[f][tx * 4 + c];
        #pragma unroll
        for (int r = 0; r < 8; r++) m[r] = me_s[f][ty * 8 + r];
        #pragma unroll
        for (int r = 0; r < 8; r++)
            #pragma unroll
            for (int c = 0; c < 4; c++) acc[r][c] += m[r] * w[c];
    }
    int d = d0 + tx * 4;
    float4 bvv = *(const float4*)(bv + d);
    #pragma unroll
    for (int r = 0; r < 8; r++) {
        int b = b0 + ty * 8 + r;
        float4 fv = *(const float4*)(feat + (size_t)b * ND + d);
        union { __half h[4]; uint2 u; } H;
        H.h[0] = __float2half_rn(fv.x + bvv.x + acc[r][0]);
        H.h[1] = __float2half_rn(fv.y + bvv.y + acc[r][1]);
        H.h[2] = __float2half_rn(fv.z + bvv.z + acc[r][2]);
        H.h[3] = __float2half_rn(fv.w + bvv.w + acc[r][3]);
        *(uint2*)(g_a1 + (size_t)b * ND + d) = H.u;
    }
}

// ------- 5a. GEMM1: hidden = relu(a1 @ W1^T + b1) -> g_hid [hi|lo] ----------
// Block 256x256, 512 threads, 16 warps 4(m)x4(n), warp 64x64, K=1024, 1 wave.
__global__ void __launch_bounds__(512, 1)
k_gemm1(const __half* __restrict__ A, const __half* __restrict__ B,
        const float* __restrict__ bias) {
    extern __shared__ char dsm[];
    uint32_t raw = smem_u32(dsm);
    const uint32_t sm0 = (raw + 1023u) & ~1023u;

    const int tid = threadIdx.x, wid = tid >> 5, lane = tid & 31;
    const int wm = wid & 3, wn = wid >> 2;
    const int bm = blockIdx.y * 256, bn = blockIdx.x * 256;
    const size_t rowb = (size_t)ND * 2;      // 2048 B per row (both A and W1)
    const int NK = ND / 64;                  // 16

    const int lrow0 = tid >> 3;              // 0..63
    const int ls    = tid & 7;
    const uint32_t lsw = (uint32_t)((ls * 16) ^ ((lrow0 & 7) * 16));

    auto load_stage = [&](int slot, int kt) {
        uint32_t sb = sm0 + slot * 65536;
        int k0b = kt * 128;
        #pragma unroll
        for (int i = 0; i < 4; i++) {        // A: 256 rows
            int r = lrow0 + i * 64;
            CPA16(sb + r * 128 + lsw,
                  (const char*)A + (size_t)(bm + r) * rowb + k0b + ls * 16, 16);
        }
        #pragma unroll
        for (int i = 0; i < 4; i++) {        // B: 256 rows (N=2048 exact)
            int r = lrow0 + i * 64;
            CPA16(sb + 32768 + r * 128 + lsw,
                  (const char*)B + (size_t)(bn + r) * rowb + k0b + ls * 16, 16);
        }
        CPA_COMMIT();
    };

    const int aRow = wm * 64 + (lane & 15);
    const uint32_t cbA  = (uint32_t)((lane >> 4) * 16);
    const uint32_t xorA = (uint32_t)((lane & 7) * 16);
    const int bRow = wn * 64 + (lane & 7) + ((lane >> 4) << 3);
    const uint32_t cbB  = (uint32_t)(((lane >> 3) & 1) * 16);
    const uint32_t xorB = (uint32_t)((lane & 7) * 16);

    float acc[4][8][4];
    #pragma unroll
    for (int i = 0; i < 4; i++)
        #pragma unroll
        for (int j = 0; j < 8; j++)
            #pragma unroll
            for (int k = 0; k < 4; k++) acc[i][j][k] = 0.f;

    uint32_t af[4][4], bf[4][4];

    load_stage(0, 0); load_stage(1, 1);

    #pragma unroll 1
    for (int ks = 0; ks < NK; ks++) {
        int slot = ks - (ks / 3) * 3;
        asm volatile("cp.async.wait_group 1;" ::: "memory");
        __syncthreads();
        if (ks + 2 < NK) {
            int s2 = (ks + 2) - ((ks + 2) / 3) * 3;
            load_stage(s2, ks + 2);
        }
        uint32_t sA = sm0 + slot * 65536;
        uint32_t sB = sA + 32768;
        #pragma unroll
        for (int kk = 0; kk < 4; kk++) {
            #pragma unroll
            for (int mt = 0; mt < 4; mt++)
                ldsm4(af[mt][0], af[mt][1], af[mt][2], af[mt][3],
                      sA + (uint32_t)(aRow + mt * 16) * 128 +
                          (((uint32_t)(32 * kk) + cbA) ^ xorA));
            #pragma unroll
            for (int nt2 = 0; nt2 < 4; nt2++)
                ldsm4(bf[nt2][0], bf[nt2][1], bf[nt2][2], bf[nt2][3],
                      sB + (uint32_t)(bRow + nt2 * 16) * 128 +
                          (((uint32_t)(32 * kk) + cbB) ^ xorB));
            #pragma unroll
            for (int mt = 0; mt < 4; mt++)
                #pragma unroll
                for (int nt2 = 0; nt2 < 4; nt2++) {
                    mma16816(acc[mt][nt2 * 2],
                             af[mt][0], af[mt][1], af[mt][2], af[mt][3],
                             bf[nt2][0], bf[nt2][1]);
                    mma16816(acc[mt][nt2 * 2 + 1],
                             af[mt][0], af[mt][1], af[mt][2], af[mt][3],
                             bf[nt2][2], bf[nt2][3]);
                }
        }
    }

    const int mBase = bm + wm * 64;
    const int nBase = bn + wn * 64;
    #pragma unroll
    for (int mt = 0; mt < 4; mt++)
        #pragma unroll
        for (int nt = 0; nt < 8; nt++)
            #pragma unroll
            for (int rs = 0; rs < 2; rs++) {
                int gm = mBase + mt * 16 + (lane >> 2) + rs * 8;
                int n  = nBase + nt * 8 + 2 * (lane & 3);
                float2 bb = *(const float2*)(bias + n);
                float h0 = fmaxf(acc[mt][nt][rs * 2 + 0] + bb.x, 0.f);
                float h1 = fmaxf(acc[mt][nt][rs * 2 + 1] + bb.y, 0.f);
                __half H0 = __float2half_rn(h0), H1 = __float2half_rn(h1);
                __half L0 = __float2half_rn(h0 - __half2float(H0));
                __half L1 = __float2half_rn(h1 - __half2float(H1));
                __half2 Hh, Ll; Hh.x = H0; Hh.y = H1; Ll.x = L0; Ll.y = L1;
                __half* ob = g_hid + (size_t)gm * (2 * NH) + n;
                *(__half2*)(ob)      = Hh;
                *(__half2*)(ob + NH) = Ll;
            }
}

// ------- 5b. GEMM2: logits = hid_hi @ W2^T + b2 (fp32 out) ------------------
// Block 256x128, 256 threads, 8 warps 4(m)x2(n), warp 64x64, K=2048, 1 wave.
__global__ void __launch_bounds__(256, 1)
k_gemm2(const __half* __restrict__ A, const __half* __restrict__ B,
        const float* __restrict__ bias, float* __restrict__ outp) {
    extern __shared__ char dsm[];
    uint32_t raw = smem_u32(dsm);
    const uint32_t sm0 = (raw + 1023u) & ~1023u;

    const int tid = threadIdx.x, wid = tid >> 5, lane = tid & 31;
    const int wm = wid >> 1, wn = wid & 1;
    const int bm = blockIdx.y * 256, bn = blockIdx.x * 128;
    const size_t rowbA = (size_t)(2 * NH) * 2;   // 8192 B (hid row, hi half used)
    const size_t rowbB = (size_t)NH * 2;         // 4096 B
    const int NK = NH / 64;                      // 32

    const int lrow0 = tid >> 3;
    const int ls    = tid & 7;
    const uint32_t lsw = (uint32_t)((ls * 16) ^ ((lrow0 & 7) * 16));

    auto load_stage = [&](int slot, int kt) {
        uint32_t sb = sm0 + slot * 49152;
        int k0b = kt * 128;
        #pragma unroll
        for (int i = 0; i < 8; i++) {
            int r = lrow0 + i * 32;
            CPA16(sb + r * 128 + lsw,
                  (const char*)A + (size_t)(bm + r) * rowbA + k0b + ls * 16, 16);
        }
        #pragma unroll
        for (int i = 0; i < 4; i++) {
            int r = lrow0 + i * 32;
            int gr = bn + r;
            bool v = gr < NC;
            CPA16(sb + 32768 + r * 128 + lsw,
                  (const char*)B + (size_t)(v ? gr : 0) * rowbB + k0b + ls * 16,
                  v ? 16 : 0);
        }
        CPA_COMMIT();
    };

    const int aRow = wm * 64 + (lane & 15);
    const uint32_t cbA  = (uint32_t)((lane >> 4) * 16);
    const uint32_t xorA = (uint32_t)((lane & 7) * 16);
    const int bRow = wn * 64 + (lane & 7) + ((lane >> 4) << 3);
    const uint32_t cbB  = (uint32_t)(((lane >> 3) & 1) * 16);
    const uint32_t xorB = (uint32_t)((lane & 7) * 16);

    float acc[4][8][4];
    #pragma unroll
    for (int i = 0; i < 4; i++)
        #pragma unroll
        for (int j = 0; j < 8; j++)
            #pragma unroll
            for (int k = 0; k < 4; k++) acc[i][j][k] = 0.f;

    uint32_t af[4][4], bf[4][4];

    load_stage(0, 0); load_stage(1, 1);

    #pragma unroll 1
    for (int ks = 0; ks < NK; ks++) {
        int slot = ks - (ks / 3) * 3;
        asm volatile("cp.async.wait_group 1;" ::: "memory");
        __syncthreads();
        if (ks + 2 < NK) {
            int s2 = (ks + 2) - ((ks + 2) / 3) * 3;
            load_stage(s2, ks + 2);
        }
        uint32_t sA = sm0 + slot * 49152;
        uint32_t sB = sA + 32768;
        #pragma unroll
        for (int kk = 0; kk < 4; kk++) {
            #pragma unroll
            for (int mt = 0; mt < 4; mt++)
                ldsm4(af[mt][0], af[mt][1], af[mt][2], af[mt][3],
                      sA + (uint32_t)(aRow + mt * 16) * 128 +
                          (((uint32_t)(32 * kk) + cbA) ^ xorA));
            #pragma unroll
            for (int nt2 = 0; nt2 < 4; nt2++)
                ldsm4(bf[nt2][0], bf[nt2][1], bf[nt2][2], bf[nt2][3],
                      sB + (uint32_t)(bRow + nt2 * 16) * 128 +
                          (((uint32_t)(32 * kk) + cbB) ^ xorB));
            #pragma unroll
            for (int mt = 0; mt < 4; mt++)
                #pragma unroll
                for (int nt2 = 0; nt2 < 4; nt2++) {
                    mma16816(acc[mt][nt2 * 2],
                             af[mt][0], af[mt][1], af[mt][2], af[mt][3],
                             bf[nt2][0], bf[nt2][1]);
                    mma16816(acc[mt][nt2 * 2 + 1],
                             af[mt][0], af[mt][1], af[mt][2], af[mt][3],
                             bf[nt2][2], bf[nt2][3]);
                }
        }
    }

    const int mBase = bm + wm * 64;
    const int nBase = bn + wn * 64;
    #pragma unroll
    for (int mt = 0; mt < 4; mt++)
        #pragma unroll
        for (int nt = 0; nt < 8; nt++)
            #pragma unroll
            for (int rs = 0; rs < 2; rs++) {
                int gm = mBase + mt * 16 + (lane >> 2) + rs * 8;
                int n  = nBase + nt * 8 + 2 * (lane & 3);
                if (n < NC) {
                    float2 bb = *(const float2*)(bias + n);
                    *(float2*)(outp + (size_t)gm * NC + n) =
                        make_float2(acc[mt][nt][rs * 2 + 0] + bb.x,
                                    acc[mt][nt][rs * 2 + 1] + bb.y);
                }
            }
}

// ------- 6. fused tail: scalar head MSE + log-softmax CE + argmax -----------
__global__ void k_tail(const float* __restrict__ Ws,
                       const float* __restrict__ bs,
                       const float* __restrict__ tgt_s,
                       const int* __restrict__ tgt_v) {
    int b = blockIdx.x, tid = threadIdx.x;   // 256 threads

    const __half* hrow = g_hid + (size_t)b * (2 * NH);
    float a = 0.f;
    for (int h = tid; h < NH; h += 256) {
        float hv = __half2float(hrow[h]) + __half2float(hrow[NH + h]);
        a += hv * Ws[h];
    }
    for (int o = 16; o; o >>= 1) a += __shfl_down_sync(0xffffffffu, a, o);
    __shared__ float sred[8];
    if ((tid & 31) == 0) sred[tid >> 5] = a;
    __syncthreads();
    if (tid == 0) {
        float t = 0.f;
        for (int w = 0; w < 8; w++) t += sred[w];
        float d = t + bs[0] - tgt_s[b];
        g_rowsq[b] = d * d;
    }
    __syncthreads();

    const float* row = g_logits + (size_t)b * NC;
    float vmax = -INFINITY; int vidx = 0x7fffffff;
    for (int c = tid; c < NC; c += 256) {
        float v = row[c];
        if (v > vmax) { vmax = v; vidx = c; }
    }
    for (int o = 16; o; o >>= 1) {
        float ov = __shfl_down_sync(0xffffffffu, vmax, o);
        int   oi = __shfl_down_sync(0xffffffffu, vidx, o);
        if (ov > vmax || (ov == vmax && oi < vidx)) { vmax = ov; vidx = oi; }
    }
    __shared__ float sv[8]; __shared__ int si[8];
    if ((tid & 31) == 0) { sv[tid >> 5] = vmax; si[tid >> 5] = vidx; }
    __syncthreads();
    __shared__ float bmax_s; __shared__ int bidx_s;
    if (tid == 0) {
        float m = sv[0]; int ix = si[0];
        for (int w = 1; w < 8; w++)
            if (sv[w] > m || (sv[w] == m && si[w] < ix)) { m = sv[w]; ix = si[w]; }
        bmax_s = m; bidx_s = ix;
    }
    __syncthreads();
    float bmax = bmax_s;
    float se = 0.f;
    for (int c = tid; c < NC; c += 256) se += expf(row[c] - bmax);
    for (int o = 16; o; o >>= 1) se += __shfl_down_sync(0xffffffffu, se, o);
    if ((tid & 31) == 0) sred[tid >> 5] = se;
    __syncthreads();
    if (tid == 0) {
        float tot = 0.f;
        for (int w = 0; w < 8; w++) tot += sred[w];
        int t = tgt_v[b];
        g_rowloss[b] = -(row[t] - bmax - logf(tot));
        g_rowcorrect[b] = (bidx_s == t) ? 1.0f : 0.0f;
    }
}

// ------- 7. final reduce ----------------------------------------------------
__global__ void k_final(float* __restrict__ out) {
    int tid = threadIdx.x;
    float l = 0.f, c = 0.f, q = 0.f;
    for (int i = tid; i < NB; i += 1024) {
        l += g_rowloss[i]; c += g_rowcorrect[i]; q += g_rowsq[i];
    }
    __shared__ float sl[1024], sc[1024], sq[1024];
    sl[tid] = l; sc[tid] = c; sq[tid] = q;
    __syncthreads();
    for (int off = 512; off > 0; off >>= 1) {
        if (tid < off) {
            sl[tid] += sl[tid + off];
            sc[tid] += sc[tid + off];
            sq[tid] += sq[tid + off];
        }
        __syncthreads();
    }
    if (tid == 0) {
        float lv = sl[0] / (float)NB;
        float ls = sq[0] / (float)NB;
        out[0] = lv + ls;
        out[1] = lv;
        out[2] = ls;
        out[3] = sc[0] / (float)NB;
    }
}

// ---------------- launch ----------------------------------------------------
extern "C" void kernel_launch(void* const* d_in, const int* in_sizes, int n_in,
                              void* d_out, int out_size) {
    const float* feature = (const float*)d_in[0];
    const float* var_flat = (const float*)d_in[1];
    const int*   seg      = (const int*)d_in[2];
    const int*   tgt_vec  = (const int*)d_in[3];
    const float* tgt_sca  = (const float*)d_in[4];
    const float* Wv = (const float*)d_in[5];
    const float* bv = (const float*)d_in[6];
    const float* W1 = (const float*)d_in[7];
    const float* b1 = (const float*)d_in[8];
    const float* W2 = (const float*)d_in[9];
    const float* b2 = (const float*)d_in[10];
    const float* Ws = (const float*)d_in[11];
    const float* bs = (const float*)d_in[12];
    float* out = (float*)d_out;
    int T = in_sizes[1] / NF;

    __half *a1_p, *w1_p, *hid_p, *w2_p;
    float* logits_p;
    cudaGetSymbolAddress((void**)&a1_p, g_a1);
    cudaGetSymbolAddress((void**)&w1_p, g_w1);
    cudaGetSymbolAddress((void**)&hid_p, g_hid);
    cudaGetSymbolAddress((void**)&w2_p, g_w2);
    cudaGetSymbolAddress((void**)&logits_p, g_logits);

    const int SMEM1 = 3 * 65536 + 1024;    // 197632
    const int SMEM2 = 3 * 49152 + 1024;    // 148480
    cudaFuncSetAttribute(k_gemm1, cudaFuncAttributeMaxDynamicSharedMemorySize, SMEM1);
    cudaFuncSetAttribute(k_gemm2, cudaFuncAttributeMaxDynamicSharedMemorySize, SMEM2);

    k_starts<<<(NB + 1 + 255) / 256, 256>>>(seg, T);
    k_means<<<NB, 256>>>(var_flat);
    k_cvt_w<<<(NH * ND / 4 + 255) / 256, 256>>>(W1, w1_p, NH * ND / 4);
    k_cvt_w<<<(NC * NH / 4 + 255) / 256, 256>>>(W2, w2_p, NC * NH / 4);
    {
        dim3 g(ND / 64, NB / 128);
        k_combined<<<g, 256>>>(feature, Wv, bv);
    }
    {   // hidden = relu(a1 @ W1^T + b1) -> g_hid [hi|lo], 128 CTAs = 1 wave
        dim3 g(NH / 256, NB / 256);
        k_gemm1<<<g, 512, SMEM1>>>(a1_p, w1_p, b1);
    }
    {   // logits = hid_hi @ W2^T + b2, 128 CTAs = 1 wave
        dim3 g(1024 / 128, NB / 256);
        k_gemm2<<<g, 256, SMEM2>>>(hid_p, w2_p, b2, logits_p);
    }
    k_tail<<<NB, 256>>>(Ws, bs, tgt_sca, tgt_vec);
    k_final<<<1, 1024>>>(out);
}

// round 13
// speedup vs baseline: 1.5638x; 1.5638x over previous
#include <cuda_runtime.h>
#include <cuda_fp16.h>
#include <math.h>
#include <stdint.h>

#define NB 4096
#define ND 1024
#define NH 2048
#define NC 1000
#define NF 32

// ---------------- scratch ---------------------------------------------------
__device__ float g_means[NB * NF];
__device__ __align__(16) __half g_a1[(size_t)NB * ND];      // fp16(combined)
__device__ __align__(16) __half g_w1[(size_t)NH * ND];      // fp16(W1)
__device__ __align__(16) __half g_hid_hi[(size_t)NB * NH];  // fp16 hi(hidden)
__device__ __align__(16) __half g_hid_lo[(size_t)NB * NH];  // fp16 lo(hidden)
__device__ __align__(16) __half g_w2[(size_t)NC * NH];      // fp16(W2)
__device__ float g_logits[(size_t)NB * NC];
__device__ float g_rowloss[NB];
__device__ float g_rowcorrect[NB];
__device__ float g_rowsq[NB];
__device__ int   g_starts[NB + 1];

// ---------------- helpers ---------------------------------------------------
__device__ __forceinline__ uint32_t smem_u32(const void* p) {
    uint32_t a;
    asm("{ .reg .u64 t; cvta.to.shared.u64 t, %1; cvt.u32.u64 %0, t; }"
        : "=r"(a) : "l"(p));
    return a;
}

__device__ __forceinline__ void ldsm4(uint32_t& r0, uint32_t& r1, uint32_t& r2,
                                      uint32_t& r3, uint32_t a) {
    asm volatile("ldmatrix.sync.aligned.m8n8.x4.shared.b16 {%0,%1,%2,%3}, [%4];"
                 : "=r"(r0), "=r"(r1), "=r"(r2), "=r"(r3) : "r"(a));
}

__device__ __forceinline__ void mma16816(float* c, uint32_t a0, uint32_t a1,
                                         uint32_t a2, uint32_t a3,
                                         uint32_t b0, uint32_t b1) {
    asm volatile(
        "mma.sync.aligned.m16n8k16.row.col.f32.f16.f16.f32 "
        "{%0,%1,%2,%3}, {%4,%5,%6,%7}, {%8,%9}, {%0,%1,%2,%3};"
        : "+f"(c[0]), "+f"(c[1]), "+f"(c[2]), "+f"(c[3])
        : "r"(a0), "r"(a1), "r"(a2), "r"(a3), "r"(b0), "r"(b1));
}

#define CPA16(sa, ga, pbytes) \
    asm volatile("cp.async.cg.shared.global [%0], [%1], 16, %2;" \
                 :: "r"(sa), "l"(ga), "r"(pbytes))
#define CPA_COMMIT() asm volatile("cp.async.commit_group;" ::: "memory")

// ---------------- 1. segment starts -----------------------------------------
__global__ void k_starts(const int* __restrict__ seg, int T) {
    int b = blockIdx.x * blockDim.x + threadIdx.x;
    if (b > NB) return;
    int lo = 0, hi = T;
    while (lo < hi) { int m = (lo + hi) >> 1; if (seg[m] < b) lo = m + 1; else hi = m; }
    g_starts[b] = lo;
}

// ---------------- 2. per-segment mean ---------------------------------------
__global__ void k_means(const float* __restrict__ vf) {
    int b = blockIdx.x;
    int start = g_starts[b], end = g_starts[b + 1];
    int tid = threadIdx.x;
    int j = tid & 7, r = tid >> 3;
    float4 acc = make_float4(0.f, 0.f, 0.f, 0.f);
    for (int row = start + r; row < end; row += 32) {
        float4 v = *(const float4*)(vf + (size_t)row * NF + j * 4);
        acc.x += v.x; acc.y += v.y; acc.z += v.z; acc.w += v.w;
    }
    __shared__ float4 s[256];
    s[tid] = acc; __syncthreads();
    for (int off = 128; off >= 8; off >>= 1) {
        if (tid < off) {
            float4 o = s[tid + off]; float4 m = s[tid];
            m.x += o.x; m.y += o.y; m.z += o.z; m.w += o.w; s[tid] = m;
        }
        __syncthreads();
    }
    if (tid < 8) {
        float inv = 1.0f / fmaxf((float)(end - start), 1.0f);
        float4 m = s[tid];
        m.x *= inv; m.y *= inv; m.z *= inv; m.w *= inv;
        *(float4*)(g_means + (size_t)b * NF + tid * 4) = m;
    }
}

// ------- 3. weight fp32 -> fp16 ---------------------------------------------
__global__ void k_cvt_w(const float* __restrict__ W, __half* __restrict__ out,
                        int total4) {
    int idx = blockIdx.x * blockDim.x + threadIdx.x;
    if (idx >= total4) return;
    float4 v = *(const float4*)(W + (size_t)idx * 4);
    union { __half h[4]; uint2 u; } H;
    H.h[0] = __float2half_rn(v.x); H.h[1] = __float2half_rn(v.y);
    H.h[2] = __float2half_rn(v.z); H.h[3] = __float2half_rn(v.w);
    *(uint2*)(out + (size_t)idx * 4) = H.u;
}

// ------- 4. combined = feature + means @ Wv^T + bv -> fp16 ------------------
__global__ void k_combined(const float* __restrict__ feat,
                           const float* __restrict__ Wv,
                           const float* __restrict__ bv) {
    __shared__ float wv_s[NF][64];
    __shared__ float me_s[NF][128];
    int d0 = blockIdx.x * 64, b0 = blockIdx.y * 128;
    int tid = threadIdx.x;
    for (int idx = tid; idx < 64 * 8; idx += 256) {
        int dd = idx >> 3, fg = (idx & 7) * 4;
        float4 v = *(const float4*)(Wv + (size_t)(d0 + dd) * NF + fg);
        wv_s[fg + 0][dd] = v.x; wv_s[fg + 1][dd] = v.y;
        wv_s[fg + 2][dd] = v.z; wv_s[fg + 3][dd] = v.w;
    }
    for (int idx = tid; idx < 128 * 8; idx += 256) {
        int bb = idx >> 3, fg = (idx & 7) * 4;
        float4 v = *(const float4*)(g_means + (size_t)(b0 + bb) * NF + fg);
        me_s[fg + 0][bb] = v.x; me_s[fg + 1][bb] = v.y;
        me_s[fg + 2][bb] = v.z; me_s[fg + 3][bb] = v.w;
    }
    __syncthreads();
    int tx = tid & 15, ty = tid >> 4;
    float acc[8][4];
    #pragma unroll
    for (int r = 0; r < 8; r++)
        #pragma unroll
        for (int c = 0; c < 4; c++) acc[r][c] = 0.f;
    #pragma unroll 4
    for (int f = 0; f < NF; f++) {
        float w[4], m[8];
        #pragma unroll
        for (int c = 0; c < 4; c++) w[c] = wv_s[f][tx * 4 + c];
        #pragma unroll
        for (int r = 0; r < 8; r++) m[r] = me_s[f][ty * 8 + r];
        #pragma unroll
        for (int r = 0; r < 8; r++)
            #pragma unroll
            for (int c = 0; c < 4; c++) acc[r][c] += m[r] * w[c];
    }
    int d = d0 + tx * 4;
    float4 bvv = *(const float4*)(bv + d);
    #pragma unroll
    for (int r = 0; r < 8; r++) {
        int b = b0 + ty * 8 + r;
        float4 fv = *(const float4*)(feat + (size_t)b * ND + d);
        union { __half h[4]; uint2 u; } H;
        H.h[0] = __float2half_rn(fv.x + bvv.x + acc[r][0]);
        H.h[1] = __float2half_rn(fv.y + bvv.y + acc[r][1]);
        H.h[2] = __float2half_rn(fv.z + bvv.z + acc[r][2]);
        H.h[3] = __float2half_rn(fv.w + bvv.w + acc[r][3]);
        *(uint2*)(g_a1 + (size_t)b * ND + d) = H.u;
    }
}

// ------- 5. fp16 mma.sync GEMM (R11-proven config) --------------------------
// Block 256(m)x128(n), 256 threads, 8 warps 4(m)x2(n), warp 64x64,
// 3-stage 48KB cp.async ring. HID: relu+hi/lo split planes; else fp32 out.
template <bool HID>
__global__ void __launch_bounds__(256, 1)
k_gemm_mma(const __half* __restrict__ A, const __half* __restrict__ B,
           const float* __restrict__ bias, float* __restrict__ outp,
           int Kp, int Nrows, int NK) {
    extern __shared__ char dsm[];
    uint32_t raw = smem_u32(dsm);
    const uint32_t sm0 = (raw + 1023u) & ~1023u;

    const int tid = threadIdx.x, wid = tid >> 5, lane = tid & 31;
    const int wm = wid >> 1, wn = wid & 1;
    const int bm = blockIdx.y * 256, bn = blockIdx.x * 128;
    const size_t rowb = (size_t)Kp * 2;

    const int lrow0 = tid >> 3;
    const int ls    = tid & 7;
    const uint32_t lsw = (uint32_t)((ls * 16) ^ ((lrow0 & 7) * 16));

    auto load_stage = [&](int slot, int kt) {
        uint32_t sb = sm0 + slot * 49152;
        int k0b = kt * 128;
        #pragma unroll
        for (int i = 0; i < 8; i++) {
            int r = lrow0 + i * 32;
            CPA16(sb + r * 128 + lsw,
                  (const char*)A + (size_t)(bm + r) * rowb + k0b + ls * 16, 16);
        }
        #pragma unroll
        for (int i = 0; i < 4; i++) {
            int r = lrow0 + i * 32;
            int gr = bn + r;
            bool v = gr < Nrows;
            CPA16(sb + 32768 + r * 128 + lsw,
                  (const char*)B + (size_t)(v ? gr : 0) * rowb + k0b + ls * 16,
                  v ? 16 : 0);
        }
        CPA_COMMIT();
    };

    const int aRow = wm * 64 + (lane & 15);
    const uint32_t cbA  = (uint32_t)((lane >> 4) * 16);
    const uint32_t xorA = (uint32_t)((lane & 7) * 16);
    const int bRow = wn * 64 + (lane & 7) + ((lane >> 4) << 3);
    const uint32_t cbB  = (uint32_t)(((lane >> 3) & 1) * 16);
    const uint32_t xorB = (uint32_t)((lane & 7) * 16);

    float acc[4][8][4];
    #pragma unroll
    for (int i = 0; i < 4; i++)
        #pragma unroll
        for (int j = 0; j < 8; j++)
            #pragma unroll
            for (int k = 0; k < 4; k++) acc[i][j][k] = 0.f;

    uint32_t af[4][4], bf[4][4];

    load_stage(0, 0); load_stage(1, 1);

    #pragma unroll 1
    for (int ks = 0; ks < NK; ks++) {
        int slot = ks - (ks / 3) * 3;
        asm volatile("cp.async.wait_group 1;" ::: "memory");
        __syncthreads();
        if (ks + 2 < NK) {
            int s2 = (ks + 2) - ((ks + 2) / 3) * 3;
            load_stage(s2, ks + 2);
        }
        uint32_t sA = sm0 + slot * 49152;
        uint32_t sB = sA + 32768;
        #pragma unroll
        for (int kk = 0; kk < 4; kk++) {
            #pragma unroll
            for (int mt = 0; mt < 4; mt++)
                ldsm4(af[mt][0], af[mt][1], af[mt][2], af[mt][3],
                      sA + (uint32_t)(aRow + mt * 16) * 128 +
                          (((uint32_t)(32 * kk) + cbA) ^ xorA));
            #pragma unroll
            for (int nt2 = 0; nt2 < 4; nt2++)
                ldsm4(bf[nt2][0], bf[nt2][1], bf[nt2][2], bf[nt2][3],
                      sB + (uint32_t)(bRow + nt2 * 16) * 128 +
                          (((uint32_t)(32 * kk) + cbB) ^ xorB));
            #pragma unroll
            for (int mt = 0; mt < 4; mt++)
                #pragma unroll
                for (int nt2 = 0; nt2 < 4; nt2++) {
                    mma16816(acc[mt][nt2 * 2],
                             af[mt][0], af[mt][1], af[mt][2], af[mt][3],
                             bf[nt2][0], bf[nt2][1]);
                    mma16816(acc[mt][nt2 * 2 + 1],
                             af[mt][0], af[mt][1], af[mt][2], af[mt][3],
                             bf[nt2][2], bf[nt2][3]);
                }
        }
    }

    const int mBase = bm + wm * 64;
    const int nBase = bn + wn * 64;
    #pragma unroll
    for (int mt = 0; mt < 4; mt++)
        #pragma unroll
        for (int nt = 0; nt < 8; nt++)
            #pragma unroll
            for (int rs = 0; rs < 2; rs++) {
                int gm = mBase + mt * 16 + (lane >> 2) + rs * 8;
                int n  = nBase + nt * 8 + 2 * (lane & 3);
                float v0 = acc[mt][nt][rs * 2 + 0];
                float v1 = acc[mt][nt][rs * 2 + 1];
                if (HID) {
                    float2 bb = *(const float2*)(bias + n);
                    float h0 = fmaxf(v0 + bb.x, 0.f), h1 = fmaxf(v1 + bb.y, 0.f);
                    __half H0 = __float2half_rn(h0), H1 = __float2half_rn(h1);
                    __half L0 = __float2half_rn(h0 - __half2float(H0));
                    __half L1 = __float2half_rn(h1 - __half2float(H1));
                    __half2 Hh, Ll; Hh.x = H0; Hh.y = H1; Ll.x = L0; Ll.y = L1;
                    *(__half2*)(g_hid_hi + (size_t)gm * NH + n) = Hh;
                    *(__half2*)(g_hid_lo + (size_t)gm * NH + n) = Ll;
                } else if (n < Nrows) {
                    float2 bb = *(const float2*)(bias + n);
                    *(float2*)(outp + (size_t)gm * NC + n) =
                        make_float2(v0 + bb.x, v1 + bb.y);
                }
            }
}

// ------- 6. fused tail: scalar head MSE + log-softmax CE + argmax -----------
__global__ void k_tail(const float* __restrict__ Ws,
                       const float* __restrict__ bs,
                       const float* __restrict__ tgt_s,
                       const int* __restrict__ tgt_v) {
    int b = blockIdx.x, tid = threadIdx.x;   // 256 threads

    const __half* hh = g_hid_hi + (size_t)b * NH;
    const __half* hl = g_hid_lo + (size_t)b * NH;
    float a = 0.f;
    for (int h = tid; h < NH; h += 256) {
        float hv = __half2float(hh[h]) + __half2float(hl[h]);
        a += hv * Ws[h];
    }
    for (int o = 16; o; o >>= 1) a += __shfl_down_sync(0xffffffffu, a, o);
    __shared__ float sred[8];
    if ((tid & 31) == 0) sred[tid >> 5] = a;
    __syncthreads();
    if (tid == 0) {
        float t = 0.f;
        for (int w = 0; w < 8; w++) t += sred[w];
        float d = t + bs[0] - tgt_s[b];
        g_rowsq[b] = d * d;
    }
    __syncthreads();

    const float* row = g_logits + (size_t)b * NC;
    float vmax = -INFINITY; int vidx = 0x7fffffff;
    for (int c = tid; c < NC; c += 256) {
        float v = row[c];
        if (v > vmax) { vmax = v; vidx = c; }
    }
    for (int o = 16; o; o >>= 1) {
        float ov = __shfl_down_sync(0xffffffffu, vmax, o);
        int   oi = __shfl_down_sync(0xffffffffu, vidx, o);
        if (ov > vmax || (ov == vmax && oi < vidx)) { vmax = ov; vidx = oi; }
    }
    __shared__ float sv[8]; __shared__ int si[8];
    if ((tid & 31) == 0) { sv[tid >> 5] = vmax; si[tid >> 5] = vidx; }
    __syncthreads();
    __shared__ float bmax_s; __shared__ int bidx_s;
    if (tid == 0) {
        float m = sv[0]; int ix = si[0];
        for (int w = 1; w < 8; w++)
            if (sv[w] > m || (sv[w] == m && si[w] < ix)) { m = sv[w]; ix = si[w]; }
        bmax_s = m; bidx_s = ix;
    }
    __syncthreads();
    float bmax = bmax_s;
    float se = 0.f;
    for (int c = tid; c < NC; c += 256) se += expf(row[c] - bmax);
    for (int o = 16; o; o >>= 1) se += __shfl_down_sync(0xffffffffu, se, o);
    if ((tid & 31) == 0) sred[tid >> 5] = se;
    __syncthreads();
    if (tid == 0) {
        float tot = 0.f;
        for (int w = 0; w < 8; w++) tot += sred[w];
        int t = tgt_v[b];
        g_rowloss[b] = -(row[t] - bmax - logf(tot));
        g_rowcorrect[b] = (bidx_s == t) ? 1.0f : 0.0f;
    }
}

// ------- 7. final reduce ----------------------------------------------------
__global__ void k_final(float* __restrict__ out) {
    int tid = threadIdx.x;
    float l = 0.f, c = 0.f, q = 0.f;
    for (int i = tid; i < NB; i += 1024) {
        l += g_rowloss[i]; c += g_rowcorrect[i]; q += g_rowsq[i];
    }
    __shared__ float sl[1024], sc[1024], sq[1024];
    sl[tid] = l; sc[tid] = c; sq[tid] = q;
    __syncthreads();
    for (int off = 512; off > 0; off >>= 1) {
        if (tid < off) {
            sl[tid] += sl[tid + off];
            sc[tid] += sc[tid + off];
            sq[tid] += sq[tid + off];
        }
        __syncthreads();
    }
    if (tid == 0) {
        float lv = sl[0] / (float)NB;
        float ls = sq[0] / (float)NB;
        out[0] = lv + ls;
        out[1] = lv;
        out[2] = ls;
        out[3] = sc[0] / (float)NB;
    }
}

// ---------------- launch ----------------------------------------------------
extern "C" void kernel_launch(void* const* d_in, const int* in_sizes, int n_in,
                              void* d_out, int out_size) {
    const float* feature = (const float*)d_in[0];
    const float* var_flat = (const float*)d_in[1];
    const int*   seg      = (const int*)d_in[2];
    const int*   tgt_vec  = (const int*)d_in[3];
    const float* tgt_sca  = (const float*)d_in[4];
    const float* Wv = (const float*)d_in[5];
    const float* bv = (const float*)d_in[6];
    const float* W1 = (const float*)d_in[7];
    const float* b1 = (const float*)d_in[8];
    const float* W2 = (const float*)d_in[9];
    const float* b2 = (const float*)d_in[10];
    const float* Ws = (const float*)d_in[11];
    const float* bs = (const float*)d_in[12];
    float* out = (float*)d_out;
    int T = in_sizes[1] / NF;

    __half *a1_p, *w1_p, *hidhi_p, *w2_p;
    float* logits_p;
    cudaGetSymbolAddress((void**)&a1_p, g_a1);
    cudaGetSymbolAddress((void**)&w1_p, g_w1);
    cudaGetSymbolAddress((void**)&hidhi_p, g_hid_hi);
    cudaGetSymbolAddress((void**)&w2_p, g_w2);
    cudaGetSymbolAddress((void**)&logits_p, g_logits);

    const int SMEMG = 3 * 49152 + 1024;    // 148480
    cudaFuncSetAttribute(k_gemm_mma<true>,
                         cudaFuncAttributeMaxDynamicSharedMemorySize, SMEMG);
    cudaFuncSetAttribute(k_gemm_mma<false>,
                         cudaFuncAttributeMaxDynamicSharedMemorySize, SMEMG);

    k_starts<<<(NB + 1 + 255) / 256, 256>>>(seg, T);
    k_means<<<NB, 256>>>(var_flat);
    k_cvt_w<<<(NH * ND / 4 + 255) / 256, 256>>>(W1, w1_p, NH * ND / 4);
    k_cvt_w<<<(NC * NH / 4 + 255) / 256, 256>>>(W2, w2_p, NC * NH / 4);
    {
        dim3 g(ND / 64, NB / 128);
        k_combined<<<g, 256>>>(feature, Wv, bv);
    }
    {   // hidden = relu(a1 @ W1^T + b1) -> g_hid_hi / g_hid_lo, K=1024
        dim3 g(NH / 128, NB / 256);
        k_gemm_mma<true><<<g, 256, SMEMG>>>(a1_p, w1_p, b1, nullptr,
                                            ND, NH, ND / 64);
    }
    {   // logits = hid_hi @ W2^T + b2, K=2048, 128 CTAs = 1 wave
        dim3 g(1024 / 128, NB / 256);
        k_gemm_mma<false><<<g, 256, SMEMG>>>(hidhi_p, w2_p, b2, logits_p,
                                             NH, NC, NH / 64);
    }
    k_tail<<<NB, 256>>>(Ws, bs, tgt_sca, tgt_vec);
    k_final<<<1, 1024>>>(out);
}